// round 7
// baseline (speedup 1.0000x reference)
#include <cuda_runtime.h>
#include <stdint.h>

#define N1 8192
#define N2 8192
#define D  1024
#define C  128
#define NTY 8

// ---------------- device scratch (static: no runtime allocation) ----------------
__device__ float g_sl1[N1 * C];          // gathered slot slices of ft_1  (4 MB)
__device__ float g_sl2[N2 * C];          // gathered slot slices of ft_2  (4 MB)
__device__ int   g_perm1[N1];
__device__ int   g_perm2[N2];
__device__ int   g_start1[NTY], g_cnt1[NTY];
__device__ int   g_start2[NTY], g_cnt2[NTY];
__device__ int   g_tilePrefix[NTY + 1];
__device__ int   g_totalTiles;
__device__ int   g_is64;                 // 1 if type arrays are int64, 0 if int32

// ---------------- dtype detection --------------------------------------------
// If types are int64 (values 0..7), every odd int32 word is 0. If int32, odd
// words are themselves type values (nonzero w.p. 7/8 each). Scan first 8192
// int32 words (safe for both layouts).
__global__ void detect_kernel(const int* __restrict__ tyraw) {
    __shared__ int sAny;
    if (threadIdx.x == 0) sAny = 0;
    __syncthreads();
    int any = 0;
    for (int i = threadIdx.x; i < 4096; i += blockDim.x)
        any |= (tyraw[2 * i + 1] != 0);
    if (any) atomicOr(&sAny, 1);
    __syncthreads();
    if (threadIdx.x == 0) g_is64 = sAny ? 0 : 1;
}

__device__ __forceinline__ int load_type(const void* ty, int i, int is64) {
    int t = is64 ? (int)((const long long*)ty)[i] : ((const int*)ty)[i];
    return t & 7;
}

// ---------------- counting sort (stable compaction per type bin) ----------------
__global__ void compact_kernel(const void* __restrict__ ty1,
                               const void* __restrict__ ty2) {
    __shared__ int sTy[N1];
    __shared__ int sBase;
    const int which = blockIdx.x >> 3;
    const int t     = blockIdx.x & 7;
    const void* ty = which ? ty2 : ty1;
    int* perm      = which ? g_perm2 : g_perm1;
    const int n = which ? N2 : N1;
    const int tid = threadIdx.x;
    const int is64 = g_is64;

    if (tid == 0) sBase = 0;
    __syncthreads();
    for (int i = tid; i < n; i += blockDim.x) sTy[i] = load_type(ty, i, is64);
    __syncthreads();

    int lc = 0;
    for (int i = tid; i < n; i += blockDim.x) lc += (sTy[i] < t) ? 1 : 0;
#pragma unroll
    for (int o = 16; o > 0; o >>= 1) lc += __shfl_down_sync(0xffffffffu, lc, o);
    if ((tid & 31) == 0) atomicAdd(&sBase, lc);
    __syncthreads();

    if (tid < 32) {
        int off = sBase;
        for (int base = 0; base < n; base += 32) {
            int i = base + tid;
            int e = (sTy[i] == t) ? 1 : 0;
            unsigned m = __ballot_sync(0xffffffffu, e != 0);
            if (e) perm[off + __popc(m & ((1u << tid) - 1u))] = i;
            off += __popc(m);
        }
        if (tid == 0) {
            if (which) { g_start2[t] = sBase; g_cnt2[t] = off - sBase; }
            else       { g_start1[t] = sBase; g_cnt1[t] = off - sBase; }
        }
    }
}

// ---------------- tile plan: prefix of per-type tile counts ----------------
__global__ void plan_kernel() {
    int tp = 0;
    for (int t = 0; t < NTY; t++) {
        g_tilePrefix[t] = tp;
        int gm = (g_cnt1[t] + 127) >> 7;
        int gn = (g_cnt2[t] + 127) >> 7;
        tp += gm * gn;
    }
    g_tilePrefix[NTY] = tp;
    g_totalTiles = tp;
}

// ---------------- gather slot slices (1 warp per row, float4 coalesced) --------
__global__ void gather_kernel(const float* __restrict__ ft1,
                              const float* __restrict__ ft2,
                              const void* __restrict__ ty1,
                               const void* __restrict__ ty2) {
    int gw   = (blockIdx.x * blockDim.x + threadIdx.x) >> 5;
    int lane = threadIdx.x & 31;
    const int is64 = g_is64;
    const float* ft;
    const void* ty;
    float* dst;
    int r;
    if (gw < N1) { ft = ft1; ty = ty1; dst = g_sl1; r = gw; }
    else         { ft = ft2; ty = ty2; dst = g_sl2; r = gw - N1; }
    int t = load_type(ty, r, is64);
    const float4* src = (const float4*)(ft + (size_t)r * D + (size_t)t * C);
    float4* d = (float4*)(dst + (size_t)r * C);
    d[lane] = src[lane];
}

// ---------------- cross GEMM: out = sl1 @ sl2^T, K=128, all 8192x8192 ----------
// 128x128 tile, 256 threads, 8x8 microtile, double-buffered smem (1 sync/ktile).
__global__ __launch_bounds__(256, 2)
void cross_gemm(float* __restrict__ out) {
    __shared__ __align__(16) float As[2][8][128];
    __shared__ __align__(16) float Bs[2][8][128];
    const int tid  = threadIdx.x;
    const int bi   = blockIdx.y, bj = blockIdx.x;
    const int lrow = tid >> 1;
    const int lcol = (tid & 1) << 2;
    const float* Ag = g_sl1 + (size_t)(bi * 128 + lrow) * C + lcol;
    const float* Bg = g_sl2 + (size_t)(bj * 128 + lrow) * C + lcol;
    const int row0 = (tid >> 4) << 3;
    const int col0 = (tid & 15) << 3;

    float acc[8][8];
#pragma unroll
    for (int i = 0; i < 8; i++)
#pragma unroll
        for (int j = 0; j < 8; j++) acc[i][j] = 0.f;

    {   // stage k-tile 0
        float4 a4 = *(const float4*)Ag;
        float4 b4 = *(const float4*)Bg;
        As[0][lcol + 0][lrow] = a4.x; As[0][lcol + 1][lrow] = a4.y;
        As[0][lcol + 2][lrow] = a4.z; As[0][lcol + 3][lrow] = a4.w;
        Bs[0][lcol + 0][lrow] = b4.x; Bs[0][lcol + 1][lrow] = b4.y;
        Bs[0][lcol + 2][lrow] = b4.z; Bs[0][lcol + 3][lrow] = b4.w;
    }
    __syncthreads();

    float (*As_c)[128] = As[0], (*As_n)[128] = As[1];
    float (*Bs_c)[128] = Bs[0], (*Bs_n)[128] = Bs[1];

#pragma unroll 1
    for (int kt = 0; kt < 16; kt++) {
        float4 na, nb;
        const bool pf = (kt < 15);
        if (pf) {
            na = *(const float4*)(Ag + (kt + 1) * 8);
            nb = *(const float4*)(Bg + (kt + 1) * 8);
        }
#pragma unroll
        for (int k = 0; k < 8; k++) {
            float a[8], b[8];
            *(float4*)&a[0] = *(const float4*)&As_c[k][row0];
            *(float4*)&a[4] = *(const float4*)&As_c[k][row0 + 4];
            *(float4*)&b[0] = *(const float4*)&Bs_c[k][col0];
            *(float4*)&b[4] = *(const float4*)&Bs_c[k][col0 + 4];
#pragma unroll
            for (int i = 0; i < 8; i++)
#pragma unroll
                for (int j = 0; j < 8; j++)
                    acc[i][j] = fmaf(a[i], b[j], acc[i][j]);
        }
        if (pf) {
            As_n[lcol + 0][lrow] = na.x; As_n[lcol + 1][lrow] = na.y;
            As_n[lcol + 2][lrow] = na.z; As_n[lcol + 3][lrow] = na.w;
            Bs_n[lcol + 0][lrow] = nb.x; Bs_n[lcol + 1][lrow] = nb.y;
            Bs_n[lcol + 2][lrow] = nb.z; Bs_n[lcol + 3][lrow] = nb.w;
            __syncthreads();
            float (*tA)[128] = As_c; As_c = As_n; As_n = tA;
            float (*tB)[128] = Bs_c; Bs_c = Bs_n; Bs_n = tB;
        }
    }

    float* obase = out + (size_t)(bi * 128 + row0) * N2 + (size_t)(bj * 128 + col0);
#pragma unroll
    for (int i = 0; i < 8; i++) {
        *(float4*)(obase + (size_t)i * N2)     = make_float4(acc[i][0], acc[i][1], acc[i][2], acc[i][3]);
        *(float4*)(obase + (size_t)i * N2 + 4) = make_float4(acc[i][4], acc[i][5], acc[i][6], acc[i][7]);
    }
}

// ---------------- same-type block GEMM: full K=1024, overwrite same pairs ------
__global__ __launch_bounds__(256, 2)
void same_gemm(const float* __restrict__ ft1, const float* __restrict__ ft2,
               float* __restrict__ out) {
    __shared__ __align__(16) float As[2][8][128];
    __shared__ __align__(16) float Bs[2][8][128];
    __shared__ int sRowG[128];
    __shared__ int sColG[128];
    const int tid = threadIdx.x;

    const int total = g_totalTiles;
    for (int tile = blockIdx.x; tile < total; tile += gridDim.x) {
        int t = 0;
        while (tile >= g_tilePrefix[t + 1]) t++;
        const int local = tile - g_tilePrefix[t];
        const int m = g_cnt1[t], n = g_cnt2[t];
        const int gn = (n + 127) >> 7;
        const int ti = local / gn, tj = local % gn;
        const int mbase = ti * 128, nbase = tj * 128;

        __syncthreads();  // protect sRowG/sColG reuse across grid-stride tiles
        if (tid < 128) {
            int ii = mbase + tid;
            sRowG[tid] = (ii < m) ? g_perm1[g_start1[t] + ii] : -1;
            int jj = nbase + tid;
            sColG[tid] = (jj < n) ? g_perm2[g_start2[t] + jj] : -1;
        }
        __syncthreads();

        const int lrow = tid >> 1;
        const int lcol = (tid & 1) << 2;
        const int ar = sRowG[lrow];
        const int br = sColG[lrow];
        // invalid (padded) rows load a dummy row; their outputs are never stored
        const float* Ag = ft1 + (size_t)(ar < 0 ? 0 : ar) * D + lcol;
        const float* Bg = ft2 + (size_t)(br < 0 ? 0 : br) * D + lcol;
        const int row0 = (tid >> 4) << 3;
        const int col0 = (tid & 15) << 3;

        float acc[8][8];
#pragma unroll
        for (int i = 0; i < 8; i++)
#pragma unroll
            for (int j = 0; j < 8; j++) acc[i][j] = 0.f;

        {
            float4 a4 = *(const float4*)Ag;
            float4 b4 = *(const float4*)Bg;
            As[0][lcol + 0][lrow] = a4.x; As[0][lcol + 1][lrow] = a4.y;
            As[0][lcol + 2][lrow] = a4.z; As[0][lcol + 3][lrow] = a4.w;
            Bs[0][lcol + 0][lrow] = b4.x; Bs[0][lcol + 1][lrow] = b4.y;
            Bs[0][lcol + 2][lrow] = b4.z; Bs[0][lcol + 3][lrow] = b4.w;
        }
        __syncthreads();

        float (*As_c)[128] = As[0], (*As_n)[128] = As[1];
        float (*Bs_c)[128] = Bs[0], (*Bs_n)[128] = Bs[1];

#pragma unroll 1
        for (int kt = 0; kt < 128; kt++) {
            float4 na, nb;
            const bool pf = (kt < 127);
            if (pf) {
                na = *(const float4*)(Ag + (kt + 1) * 8);
                nb = *(const float4*)(Bg + (kt + 1) * 8);
            }
#pragma unroll
            for (int k = 0; k < 8; k++) {
                float a[8], b[8];
                *(float4*)&a[0] = *(const float4*)&As_c[k][row0];
                *(float4*)&a[4] = *(const float4*)&As_c[k][row0 + 4];
                *(float4*)&b[0] = *(const float4*)&Bs_c[k][col0];
                *(float4*)&b[4] = *(const float4*)&Bs_c[k][col0 + 4];
#pragma unroll
                for (int i = 0; i < 8; i++)
#pragma unroll
                    for (int j = 0; j < 8; j++)
                        acc[i][j] = fmaf(a[i], b[j], acc[i][j]);
            }
            if (pf) {
                As_n[lcol + 0][lrow] = na.x; As_n[lcol + 1][lrow] = na.y;
                As_n[lcol + 2][lrow] = na.z; As_n[lcol + 3][lrow] = na.w;
                Bs_n[lcol + 0][lrow] = nb.x; Bs_n[lcol + 1][lrow] = nb.y;
                Bs_n[lcol + 2][lrow] = nb.z; Bs_n[lcol + 3][lrow] = nb.w;
                __syncthreads();
                float (*tA)[128] = As_c; As_c = As_n; As_n = tA;
                float (*tB)[128] = Bs_c; Bs_c = Bs_n; Bs_n = tB;
            }
        }

        // scattered epilogue: out[row][col] for valid permuted indices
        int cols[8];
#pragma unroll
        for (int j = 0; j < 8; j++) cols[j] = sColG[col0 + j];
#pragma unroll
        for (int i = 0; i < 8; i++) {
            int r = sRowG[row0 + i];
            if (r >= 0) {
                float* orow = out + (size_t)r * N2;
#pragma unroll
                for (int j = 0; j < 8; j++)
                    if (cols[j] >= 0) orow[cols[j]] = acc[i][j];
            }
        }
    }
}

// -------------------------------- launch ---------------------------------------
extern "C" void kernel_launch(void* const* d_in, const int* in_sizes, int n_in,
                              void* d_out, int out_size) {
    const float* ft1 = (const float*)d_in[0];
    const float* ft2 = (const float*)d_in[1];
    const void*  ty1 = d_in[2];
    const void*  ty2 = d_in[3];
    float* out = (float*)d_out;

    detect_kernel<<<1, 256>>>((const int*)ty1);
    compact_kernel<<<16, 256>>>(ty1, ty2);
    plan_kernel<<<1, 1>>>();
    gather_kernel<<<(N1 + N2) / 8, 256>>>(ft1, ft2, ty1, ty2);

    dim3 gc(N2 / 128, N1 / 128);
    cross_gemm<<<gc, 256>>>(out);             // writes every output element (cross)
    same_gemm<<<1024, 256>>>(ft1, ft2, out);  // overwrites same-type pairs (full)
}